// round 5
// baseline (speedup 1.0000x reference)
#include <cuda_runtime.h>
#include <cuda_bf16.h>
#include <math.h>

#define NBINS 128
#define NFREQ 64
#define NKERN 3
#define MLPH  64
#define KPB   14   // keys per block -> grid 586 <= 592 (148 SMs x 4 blocks): one balanced wave
#define TPB   256  // 2 halves of 128 bins; each half handles 7 keys

// Fourier coefficient table: per (f, chunk, bin) float4.
// 12 coefs per (b,f): [A0, A1c, A1s, A2c, A2s, A3c, A3s, A4c, A4s, A5c, A5s, 0]
// pairing with features  [mag, m*c1, m*s1, m*c2, m*s2, m*c3, m*s3, m*c4, m*s4, m*c5, m*s5, 0]
__device__ float4 g_cf[NFREQ * 3 * NBINS];

__device__ __forceinline__ void fma2(unsigned long long& acc, unsigned long long a, unsigned long long b) {
    asm("fma.rn.f32x2 %0, %1, %2, %0;" : "+l"(acc) : "l"(a), "l"(b));
}
__device__ __forceinline__ float2 unpack2(unsigned long long v) {
    float2 r;
    asm("mov.b64 {%0, %1}, %2;" : "=f"(r.x), "=f"(r.y) : "l"(v));
    return r;
}

// exp(kappa*(cos(theta-mu_eff)-1)) = e^-k * [I0(k) + 2*sum_k Ik(k) cos(k*(theta-mu_eff))]
// Collapse m-dimension: C[b,f,:] pairs with per-key features of theta.
__global__ void precompute_fourier(const float* __restrict__ mu,
                                   const float* __restrict__ kappa,
                                   const float* __restrict__ weight,
                                   const float* __restrict__ ref_angles) {
    int idx = blockIdx.x * blockDim.x + threadIdx.x;
    if (idx >= NBINS * NFREQ) return;
    int b = idx / NFREQ;
    int f = idx % NFREQ;
    float C[12];
    #pragma unroll
    for (int i = 0; i < 12; i++) C[i] = 0.f;

    const float fact[6] = {1.f, 1.f, 2.f, 6.f, 24.f, 120.f};
    for (int m = 0; m < NKERN; m++) {
        int off = (b * NFREQ + f) * NKERN + m;
        float kp = kappa[off];
        float w  = weight[off];
        float me = mu[off] + ref_angles[f];
        float x  = 0.5f * kp;
        float ek = expf(-kp);
        // modified Bessel I_k(kp) via power series (fast convergence for moderate kp)
        float I[6];
        #pragma unroll
        for (int kk = 0; kk < 6; kk++) {
            float term = powf(x, (float)kk) / fact[kk];
            float s = term;
            #pragma unroll
            for (int t = 1; t <= 10; t++) {
                term *= x * x / ((float)t * (float)(t + kk));
                s += term;
            }
            I[kk] = s;
        }
        float cm, sm;
        sincosf(me, &sm, &cm);
        C[0] += w * ek * I[0];
        float ck = cm, sk = sm;
        #pragma unroll
        for (int kk = 1; kk <= 5; kk++) {
            C[2 * kk - 1] += 2.f * w * ek * I[kk] * ck;
            C[2 * kk]     += 2.f * w * ek * I[kk] * sk;
            float cn = ck * cm - sk * sm;
            float sn = sk * cm + ck * sm;
            ck = cn; sk = sn;
        }
    }
    C[11] = 0.f;
    g_cf[(f * 3 + 0) * NBINS + b] = make_float4(C[0], C[1], C[2],  C[3]);
    g_cf[(f * 3 + 1) * NBINS + b] = make_float4(C[4], C[5], C[6],  C[7]);
    g_cf[(f * 3 + 2) * NBINS + b] = make_float4(C[8], C[9], C[10], C[11]);
}

__global__ __launch_bounds__(TPB, 4)
void key_pruning_main(const float2* __restrict__ K2,      // [N*64] (x,y) pairs
                      const int*    __restrict__ pos,
                      const float*  __restrict__ bias,
                      const float*  __restrict__ W1,      // [64][128]
                      const float*  __restrict__ b1,      // [64]
                      const float*  __restrict__ W2,      // [64]
                      const float*  __restrict__ b2,      // [1]
                      const float*  __restrict__ araw,    // [3]
                      float*        __restrict__ out,
                      int n) {
    __shared__ union SU {
        float4 X[NFREQ * KPB * 3];   // features [f][kk][chunk], 42 KB
        struct {
            float sl[KPB * NBINS];   // logits
            float w1[MLPH * 129];
            float h[KPB * MLPH];
            float b1w2[2 * MLPH];
        } m;                          // ~43.3 KB
    } u;

    const int tid  = threadIdx.x;
    const int bin  = tid & (NBINS - 1);
    const int half = tid >> 7;               // 0: keys 0-6, 1: keys 7-13
    const int key0 = blockIdx.x * KPB;

    // ---- Phase 1: build features mag*{1, cos k, sin k} via rotation recurrence ----
    for (int i = tid; i < KPB * NFREQ; i += TPB) {
        int kk = i / NFREQ;
        int f  = i & (NFREQ - 1);
        int key = key0 + kk; if (key >= n) key = n - 1;
        float2 v = K2[key * NFREQ + f];
        float r2 = fmaf(v.x, v.x, v.y * v.y);
        r2 = fmaxf(r2, 1e-30f);
        float rinv = rsqrtf(r2);
        float mag = r2 * rinv;
        float c1 = v.x * rinv, s1 = v.y * rinv;
        float c2 = c1 * c1 - s1 * s1,  s2 = 2.f * c1 * s1;
        float c3 = c2 * c1 - s2 * s1,  s3 = s2 * c1 + c2 * s1;
        float c4 = c3 * c1 - s3 * s1,  s4 = s3 * c1 + c3 * s1;
        float c5 = c4 * c1 - s4 * s1,  s5 = s4 * c1 + c4 * s1;
        int base = (f * KPB + kk) * 3;
        u.X[base + 0] = make_float4(mag,       mag * c1, mag * s1, mag * c2);
        u.X[base + 1] = make_float4(mag * s2,  mag * c3, mag * s3, mag * c4);
        u.X[base + 2] = make_float4(mag * s4,  mag * c5, mag * s5, 0.f);
    }
    __syncthreads();

    // ---- Phase 2: logits GEMM with packed f32x2 FMA. Thread = (bin, key-half). ----
    unsigned long long acc[7];
    #pragma unroll
    for (int j = 0; j < 7; j++) acc[j] = 0ull;

    const int kbase = half * 7;
    const ulonglong2* __restrict__ Cp = (const ulonglong2*)g_cf;
    const ulonglong2* __restrict__ Xp = (const ulonglong2*)u.X;

    #pragma unroll 2
    for (int f = 0; f < NFREQ; f++) {
        ulonglong2 g0 = Cp[(f * 3 + 0) * NBINS + bin];
        ulonglong2 g1 = Cp[(f * 3 + 1) * NBINS + bin];
        ulonglong2 g2 = Cp[(f * 3 + 2) * NBINS + bin];
        #pragma unroll
        for (int j = 0; j < 7; j++) {
            int xb = (f * KPB + kbase + j) * 3;
            ulonglong2 a0 = Xp[xb + 0];
            ulonglong2 a1 = Xp[xb + 1];
            ulonglong2 a2 = Xp[xb + 2];
            fma2(acc[j], a0.x, g0.x);
            fma2(acc[j], a0.y, g0.y);
            fma2(acc[j], a1.x, g1.x);
            fma2(acc[j], a1.y, g1.y);
            fma2(acc[j], a2.x, g2.x);
            fma2(acc[j], a2.y, g2.y);
        }
    }
    __syncthreads();   // X dead; union flips to logits/MLP view

    float bb = bias[bin];
    #pragma unroll
    for (int j = 0; j < 7; j++) {
        float2 p = unpack2(acc[j]);
        u.m.sl[(kbase + j) * NBINS + bin] = p.x + p.y + bb;
    }

    // ---- Phase 3: stage W1 (padded stride 129), b1, W2 ----
    for (int i = tid; i < MLPH * NBINS; i += TPB)
        u.m.w1[(i >> 7) * 129 + (i & 127)] = W1[i];
    if (tid < MLPH) {
        u.m.b1w2[tid]        = b1[tid];
        u.m.b1w2[MLPH + tid] = W2[tid];
    }
    __syncthreads();

    // ---- Phase 4: layer 1 (relu) with W2 folded in. KPB*64 = 896 tasks ----
    for (int t = 0; t < KPB * MLPH; t += TPB) {
        int task = t + tid;
        if (task < KPB * MLPH) {
            int kk = task >> 6;
            int j  = task & 63;
            float a = u.m.b1w2[j];
            const float* lr = &u.m.sl[kk * NBINS];
            const float* wr = &u.m.w1[j * 129];
            #pragma unroll 16
            for (int b = 0; b < NBINS; b++) a = fmaf(lr[b], wr[b], a);
            a = fmaxf(a, 0.f);
            u.m.h[kk * MLPH + j] = a * u.m.b1w2[MLPH + j];
        }
    }
    __syncthreads();

    // ---- Phase 5: reduce, position weight, sigmoid ----
    if (tid < KPB && (key0 + tid) < n) {
        float s = b2[0];
        #pragma unroll 16
        for (int j = 0; j < MLPH; j++) s += u.m.h[tid * MLPH + j];

        int p = pos[key0 + tid];
        float lp = log10f(fmaxf((float)p, 1.0f));
        float a0 = log1pf(expf(araw[0]));
        float a1 = log1pf(expf(araw[1]));
        float a2 = log1pf(expf(araw[2]));
        float w;
        if (lp < 3.f)      w = a0;
        else if (lp < 4.f) w = a0 + (a1 - a0) * (lp - 3.f);
        else if (lp < 5.f) w = a1 + (a2 - a1) * (lp - 4.f);
        else               w = a2;

        float z = s * w;
        out[key0 + tid] = 1.f / (1.f + expf(-z));
    }
}

extern "C" void kernel_launch(void* const* d_in, const int* in_sizes, int n_in,
                              void* d_out, int out_size) {
    const float* K      = (const float*)d_in[0];
    const int*   pos    = (const int*)  d_in[1];
    const float* ra     = (const float*)d_in[2];
    const float* mu     = (const float*)d_in[3];
    const float* kappa  = (const float*)d_in[4];
    const float* weight = (const float*)d_in[5];
    const float* bias   = (const float*)d_in[6];
    const float* W1     = (const float*)d_in[7];
    const float* b1     = (const float*)d_in[8];
    const float* W2     = (const float*)d_in[9];
    const float* b2     = (const float*)d_in[10];
    const float* araw   = (const float*)d_in[11];

    int n = in_sizes[1];   // number of keys (key_positions length)

    precompute_fourier<<<(NBINS * NFREQ + 255) / 256, 256>>>(mu, kappa, weight, ra);

    int grid = (n + KPB - 1) / KPB;
    key_pruning_main<<<grid, TPB>>>((const float2*)K, pos, bias, W1, b1, W2, b2, araw,
                                    (float*)d_out, n);
}

// round 6
// speedup vs baseline: 1.2746x; 1.2746x over previous
#include <cuda_runtime.h>
#include <cuda_bf16.h>
#include <math.h>

#define NBINS 128
#define NFREQ 64
#define NKERN 3
#define MLPH  64
#define KPB   28   // keys per block -> grid 293; 2 blocks/SM -> single balanced wave
#define TPB   256  // 64 bin-pairs x 4 key-quarters

// Fourier coefficient table: per (f, chunk, bin) float4.
// 12 coefs per (b,f): [A0, A1c, A1s, A2c, A2s, A3c, A3s, A4c, A4s, A5c, A5s, 0]
__device__ float4 g_cf[NFREQ * 3 * NBINS];

__device__ __forceinline__ void fma2(unsigned long long& acc, unsigned long long a, unsigned long long b) {
    asm("fma.rn.f32x2 %0, %1, %2, %0;" : "+l"(acc) : "l"(a), "l"(b));
}
__device__ __forceinline__ float2 unpack2(unsigned long long v) {
    float2 r;
    asm("mov.b64 {%0, %1}, %2;" : "=f"(r.x), "=f"(r.y) : "l"(v));
    return r;
}

__global__ void precompute_fourier(const float* __restrict__ mu,
                                   const float* __restrict__ kappa,
                                   const float* __restrict__ weight,
                                   const float* __restrict__ ref_angles) {
    int idx = blockIdx.x * blockDim.x + threadIdx.x;
    if (idx >= NBINS * NFREQ) return;
    int b = idx / NFREQ;
    int f = idx % NFREQ;
    float C[12];
    #pragma unroll
    for (int i = 0; i < 12; i++) C[i] = 0.f;

    const float fact[6] = {1.f, 1.f, 2.f, 6.f, 24.f, 120.f};
    for (int m = 0; m < NKERN; m++) {
        int off = (b * NFREQ + f) * NKERN + m;
        float kp = kappa[off];
        float w  = weight[off];
        float me = mu[off] + ref_angles[f];
        float x  = 0.5f * kp;
        float ek = expf(-kp);
        float I[6];
        #pragma unroll
        for (int kk = 0; kk < 6; kk++) {
            float term = powf(x, (float)kk) / fact[kk];
            float s = term;
            #pragma unroll
            for (int t = 1; t <= 10; t++) {
                term *= x * x / ((float)t * (float)(t + kk));
                s += term;
            }
            I[kk] = s;
        }
        float cm, sm;
        sincosf(me, &sm, &cm);
        C[0] += w * ek * I[0];
        float ck = cm, sk = sm;
        #pragma unroll
        for (int kk = 1; kk <= 5; kk++) {
            C[2 * kk - 1] += 2.f * w * ek * I[kk] * ck;
            C[2 * kk]     += 2.f * w * ek * I[kk] * sk;
            float cn = ck * cm - sk * sm;
            float sn = sk * cm + ck * sm;
            ck = cn; sk = sn;
        }
    }
    C[11] = 0.f;
    g_cf[(f * 3 + 0) * NBINS + b] = make_float4(C[0], C[1], C[2],  C[3]);
    g_cf[(f * 3 + 1) * NBINS + b] = make_float4(C[4], C[5], C[6],  C[7]);
    g_cf[(f * 3 + 2) * NBINS + b] = make_float4(C[8], C[9], C[10], C[11]);
}

// dynamic smem layout:
//   X view:   float4 X[NFREQ*KPB*3]            = 86016 bytes
//   MLP view: float sl[KPB*NBINS]  @ 0         (3584 floats)
//             float w1[MLPH*129]   @ 3584      (8256 floats)
//             float h[KPB*MLPH]    @ 11840     (1792 floats)
//             float b1w2[2*MLPH]   @ 13632     (128 floats)
#define SMEM_BYTES (NFREQ * KPB * 3 * 16)
#define OFF_W1   (KPB * NBINS)
#define OFF_H    (OFF_W1 + MLPH * 129)
#define OFF_B1W2 (OFF_H + KPB * MLPH)

__global__ __launch_bounds__(TPB, 2)
void key_pruning_main(const float2* __restrict__ K2,      // [N*64] (x,y) pairs
                      const int*    __restrict__ pos,
                      const float*  __restrict__ bias,
                      const float*  __restrict__ W1,      // [64][128]
                      const float*  __restrict__ b1,      // [64]
                      const float*  __restrict__ W2,      // [64]
                      const float*  __restrict__ b2,      // [1]
                      const float*  __restrict__ araw,    // [3]
                      float*        __restrict__ out,
                      int n) {
    extern __shared__ float4 smem4[];
    float4* X = smem4;
    float*  sm = (float*)smem4;

    const int tid = threadIdx.x;
    const int bp  = tid & 63;                // bins bp and bp+64
    const int kq  = tid >> 6;                // key quarter: keys [7*kq, 7*kq+7)
    const int key0 = blockIdx.x * KPB;

    // ---- Phase 1: build features mag*{1, cos k, sin k} via rotation recurrence ----
    for (int i = tid; i < KPB * NFREQ; i += TPB) {
        int kk = i / NFREQ;
        int f  = i & (NFREQ - 1);
        int key = key0 + kk; if (key >= n) key = n - 1;
        float2 v = K2[key * NFREQ + f];
        float r2 = fmaf(v.x, v.x, v.y * v.y);
        r2 = fmaxf(r2, 1e-30f);
        float rinv = rsqrtf(r2);
        float mag = r2 * rinv;
        float c1 = v.x * rinv, s1 = v.y * rinv;
        float c2 = c1 * c1 - s1 * s1,  s2 = 2.f * c1 * s1;
        float c3 = c2 * c1 - s2 * s1,  s3 = s2 * c1 + c2 * s1;
        float c4 = c3 * c1 - s3 * s1,  s4 = s3 * c1 + c3 * s1;
        float c5 = c4 * c1 - s4 * s1,  s5 = s4 * c1 + c4 * s1;
        int base = (f * KPB + kk) * 3;
        X[base + 0] = make_float4(mag,       mag * c1, mag * s1, mag * c2);
        X[base + 1] = make_float4(mag * s2,  mag * c3, mag * s3, mag * c4);
        X[base + 2] = make_float4(mag * s4,  mag * c5, mag * s5, 0.f);
    }
    __syncthreads();

    // ---- Phase 2: logits GEMM, register tile = 2 bins x 7 keys, packed f32x2 FMA ----
    unsigned long long accA[7], accB[7];
    #pragma unroll
    for (int j = 0; j < 7; j++) { accA[j] = 0ull; accB[j] = 0ull; }

    const ulonglong2* __restrict__ Cp = (const ulonglong2*)g_cf;
    const ulonglong2* __restrict__ Xp = (const ulonglong2*)X;
    const int kbase = kq * 7;

    #pragma unroll 2
    for (int f = 0; f < NFREQ; f++) {
        const ulonglong2* crow = Cp + f * 3 * NBINS;
        ulonglong2 cA0 = crow[0 * NBINS + bp];
        ulonglong2 cA1 = crow[1 * NBINS + bp];
        ulonglong2 cA2 = crow[2 * NBINS + bp];
        ulonglong2 cB0 = crow[0 * NBINS + bp + 64];
        ulonglong2 cB1 = crow[1 * NBINS + bp + 64];
        ulonglong2 cB2 = crow[2 * NBINS + bp + 64];
        #pragma unroll
        for (int j = 0; j < 7; j++) {
            int xb = (f * KPB + kbase + j) * 3;
            ulonglong2 a0 = Xp[xb + 0];
            ulonglong2 a1 = Xp[xb + 1];
            ulonglong2 a2 = Xp[xb + 2];
            fma2(accA[j], a0.x, cA0.x);
            fma2(accB[j], a0.x, cB0.x);
            fma2(accA[j], a0.y, cA0.y);
            fma2(accB[j], a0.y, cB0.y);
            fma2(accA[j], a1.x, cA1.x);
            fma2(accB[j], a1.x, cB1.x);
            fma2(accA[j], a1.y, cA1.y);
            fma2(accB[j], a1.y, cB1.y);
            fma2(accA[j], a2.x, cA2.x);
            fma2(accB[j], a2.x, cB2.x);
            fma2(accA[j], a2.y, cA2.y);
            fma2(accB[j], a2.y, cB2.y);
        }
    }
    __syncthreads();   // X dead; smem flips to logits/MLP view

    float bbA = bias[bp];
    float bbB = bias[bp + 64];
    #pragma unroll
    for (int j = 0; j < 7; j++) {
        float2 pa = unpack2(accA[j]);
        float2 pb = unpack2(accB[j]);
        sm[(kbase + j) * NBINS + bp]      = pa.x + pa.y + bbA;
        sm[(kbase + j) * NBINS + bp + 64] = pb.x + pb.y + bbB;
    }

    // ---- Phase 3: stage W1 (padded stride 129), b1, W2 ----
    for (int i = tid; i < MLPH * NBINS; i += TPB)
        sm[OFF_W1 + (i >> 7) * 129 + (i & 127)] = W1[i];
    if (tid < MLPH) {
        sm[OFF_B1W2 + tid]        = b1[tid];
        sm[OFF_B1W2 + MLPH + tid] = W2[tid];
    }
    __syncthreads();

    // ---- Phase 4: layer 1 (relu) with W2 folded in. KPB*64 = 1792 tasks ----
    #pragma unroll
    for (int t = 0; t < KPB * MLPH; t += TPB) {
        int task = t + tid;
        int kk = task >> 6;
        int j  = task & 63;
        float a = sm[OFF_B1W2 + j];
        const float* lr = &sm[kk * NBINS];
        const float* wr = &sm[OFF_W1 + j * 129];
        #pragma unroll 16
        for (int b = 0; b < NBINS; b++) a = fmaf(lr[b], wr[b], a);
        a = fmaxf(a, 0.f);
        sm[OFF_H + kk * MLPH + j] = a * sm[OFF_B1W2 + MLPH + j];
    }
    __syncthreads();

    // ---- Phase 5: reduce, position weight, sigmoid ----
    if (tid < KPB && (key0 + tid) < n) {
        float s = b2[0];
        #pragma unroll 16
        for (int j = 0; j < MLPH; j++) s += sm[OFF_H + tid * MLPH + j];

        int p = pos[key0 + tid];
        float lp = log10f(fmaxf((float)p, 1.0f));
        float a0 = log1pf(expf(araw[0]));
        float a1 = log1pf(expf(araw[1]));
        float a2 = log1pf(expf(araw[2]));
        float w;
        if (lp < 3.f)      w = a0;
        else if (lp < 4.f) w = a0 + (a1 - a0) * (lp - 3.f);
        else if (lp < 5.f) w = a1 + (a2 - a1) * (lp - 4.f);
        else               w = a2;

        float z = s * w;
        out[key0 + tid] = 1.f / (1.f + expf(-z));
    }
}

extern "C" void kernel_launch(void* const* d_in, const int* in_sizes, int n_in,
                              void* d_out, int out_size) {
    const float* K      = (const float*)d_in[0];
    const int*   pos    = (const int*)  d_in[1];
    const float* ra     = (const float*)d_in[2];
    const float* mu     = (const float*)d_in[3];
    const float* kappa  = (const float*)d_in[4];
    const float* weight = (const float*)d_in[5];
    const float* bias   = (const float*)d_in[6];
    const float* W1     = (const float*)d_in[7];
    const float* b1     = (const float*)d_in[8];
    const float* W2     = (const float*)d_in[9];
    const float* b2     = (const float*)d_in[10];
    const float* araw   = (const float*)d_in[11];

    int n = in_sizes[1];   // number of keys

    static int smem_set = 0;
    if (!smem_set) {
        cudaFuncSetAttribute(key_pruning_main,
                             cudaFuncAttributeMaxDynamicSharedMemorySize, SMEM_BYTES);
        smem_set = 1;
    }

    precompute_fourier<<<(NBINS * NFREQ + 255) / 256, 256>>>(mu, kappa, weight, ra);

    int grid = (n + KPB - 1) / KPB;
    key_pruning_main<<<grid, TPB, SMEM_BYTES>>>((const float2*)K, pos, bias, W1, b1, W2, b2, araw,
                                                (float*)d_out, n);
}

// round 7
// speedup vs baseline: 1.4261x; 1.1189x over previous
#include <cuda_runtime.h>
#include <cuda_bf16.h>
#include <math.h>

#define NBINS 128
#define NFREQ 64
#define NKERN 3
#define MLPH  64
#define KPB   28   // keys per block -> grid 293; 2 blocks/SM -> single balanced wave
#define TPB   256  // 8 warps; warp = 4 key-quarters x 8 bin-pairs

// Fourier coefficients, truncated at k=4 (9 coefs, padded to 10):
//   order: [A0, A1c, A1s, A2c, A2s, A3c, A3s, A4c, A4s, 0]
//   g_cfA: float4 [NFREQ][2][NBINS]  (coefs 0-3 and 4-7)
//   g_cfB: float2 [NFREQ][NBINS]     (coef 8, pad)
__device__ float4 g_cfA[NFREQ * 2 * NBINS];
__device__ float2 g_cfB[NFREQ * NBINS];

__device__ __forceinline__ void fma2(unsigned long long& acc, unsigned long long a, unsigned long long b) {
    asm("fma.rn.f32x2 %0, %1, %2, %0;" : "+l"(acc) : "l"(a), "l"(b));
}
__device__ __forceinline__ float2 unpack2(unsigned long long v) {
    float2 r;
    asm("mov.b64 {%0, %1}, %2;" : "=f"(r.x), "=f"(r.y) : "l"(v));
    return r;
}

__global__ void precompute_fourier(const float* __restrict__ mu,
                                   const float* __restrict__ kappa,
                                   const float* __restrict__ weight,
                                   const float* __restrict__ ref_angles) {
    int idx = blockIdx.x * blockDim.x + threadIdx.x;
    if (idx >= NBINS * NFREQ) return;
    int b = idx / NFREQ;
    int f = idx % NFREQ;
    float C[9];
    #pragma unroll
    for (int i = 0; i < 9; i++) C[i] = 0.f;

    #pragma unroll
    for (int m = 0; m < NKERN; m++) {
        int off = (b * NFREQ + f) * NKERN + m;
        float kp = kappa[off];
        float w  = weight[off];
        float me = mu[off] + ref_angles[f];
        float h  = 0.5f * kp;
        float h2 = h * h;
        float ek = __expf(-kp);
        // I_k(kp), k=0..4, iterative power series (8 terms each, no powf)
        float I[5];
        float hk = 1.f, kfact = 1.f;
        #pragma unroll
        for (int kk = 0; kk < 5; kk++) {
            if (kk > 0) { hk *= h; kfact *= (float)kk; }
            float term = hk / kfact;
            float s = term;
            #pragma unroll
            for (int t = 1; t <= 8; t++) {
                term *= h2 / ((float)t * (float)(t + kk));
                s += term;
            }
            I[kk] = s;
        }
        float cm, sm;
        __sincosf(me, &sm, &cm);
        float wek = w * ek;
        C[0] += wek * I[0];
        float ck = cm, sk = sm;
        #pragma unroll
        for (int kk = 1; kk <= 4; kk++) {
            float g = 2.f * wek * I[kk];
            C[2 * kk - 1] += g * ck;
            C[2 * kk]     += g * sk;
            float cn = ck * cm - sk * sm;
            float sn = sk * cm + ck * sm;
            ck = cn; sk = sn;
        }
    }
    g_cfA[(f * 2 + 0) * NBINS + b] = make_float4(C[0], C[1], C[2], C[3]);
    g_cfA[(f * 2 + 1) * NBINS + b] = make_float4(C[4], C[5], C[6], C[7]);
    g_cfB[f * NBINS + b]           = make_float2(C[8], 0.f);
}

// dynamic smem:
//   X view:   float4 X[NFREQ*KPB*3]  (48B per (f,key) feature row) = 86016 B
//   MLP view: sl[28*128] | w1[64*132] | h[28*64] | b1w2[128]      = 55808 B
#define SMEM_BYTES (NFREQ * KPB * 3 * 16)
#define OFF_W1   (KPB * NBINS)
#define OFF_H    (OFF_W1 + MLPH * 132)
#define OFF_B1W2 (OFF_H + KPB * MLPH)

__global__ __launch_bounds__(TPB, 2)
void key_pruning_main(const float2* __restrict__ K2,
                      const int*    __restrict__ pos,
                      const float*  __restrict__ bias,
                      const float*  __restrict__ W1,      // [64][128]
                      const float*  __restrict__ b1,
                      const float*  __restrict__ W2,
                      const float*  __restrict__ b2,
                      const float*  __restrict__ araw,
                      float*        __restrict__ out,
                      int n) {
    extern __shared__ float4 smem4[];
    float4* X = smem4;
    float*  sm = (float*)smem4;

    const int tid  = threadIdx.x;
    const int warp = tid >> 5;
    const int lane = tid & 31;
    const int kq   = lane >> 3;              // 0..3 -> keys [7*kq, 7*kq+7)
    const int bp8  = lane & 7;
    const int binA = warp * 16 + bp8;        // warp covers 16 consecutive bins
    const int binB = binA + 8;
    const int kbase = kq * 7;
    const int key0 = blockIdx.x * KPB;

    // ---- Phase 1: features mag*{1, cos k, sin k} (k<=4) via rotation recurrence ----
    for (int i = tid; i < KPB * NFREQ; i += TPB) {
        int kk = i / NFREQ;
        int f  = i & (NFREQ - 1);
        int key = key0 + kk; if (key >= n) key = n - 1;
        float2 v = K2[key * NFREQ + f];
        float r2 = fmaf(v.x, v.x, v.y * v.y);
        r2 = fmaxf(r2, 1e-30f);
        float rinv = rsqrtf(r2);
        float mag = r2 * rinv;
        float c1 = v.x * rinv, s1 = v.y * rinv;
        float c2 = c1 * c1 - s1 * s1,  s2 = 2.f * c1 * s1;
        float c3 = c2 * c1 - s2 * s1,  s3 = s2 * c1 + c2 * s1;
        float c4 = c3 * c1 - s3 * s1,  s4 = s3 * c1 + c3 * s1;
        int base = (f * KPB + kk) * 3;
        X[base + 0] = make_float4(mag,       mag * c1, mag * s1, mag * c2);
        X[base + 1] = make_float4(mag * s2,  mag * c3, mag * s3, mag * c4);
        X[base + 2] = make_float4(mag * s4,  0.f, 0.f, 0.f);
    }
    __syncthreads();

    // ---- Phase 2: logits GEMM, 2 bins x 7 keys per thread, packed f32x2 FMA ----
    unsigned long long accA[7], accB[7];
    #pragma unroll
    for (int j = 0; j < 7; j++) { accA[j] = 0ull; accB[j] = 0ull; }

    const ulonglong2* __restrict__ CpA = (const ulonglong2*)g_cfA;
    const unsigned long long* __restrict__ CpB = (const unsigned long long*)g_cfB;
    const ulonglong2* __restrict__ Xp2 = (const ulonglong2*)X;
    const unsigned long long* __restrict__ Xp1 = (const unsigned long long*)X;

    for (int f = 0; f < NFREQ; f++) {
        // C loads: 8 distinct bins x 16B contiguous per warp -> 1 wavefront each
        ulonglong2 cA0 = CpA[(f * 2 + 0) * NBINS + binA];
        ulonglong2 cA1 = CpA[(f * 2 + 1) * NBINS + binA];
        unsigned long long cA2 = CpB[f * NBINS + binA];
        ulonglong2 cB0 = CpA[(f * 2 + 0) * NBINS + binB];
        ulonglong2 cB1 = CpA[(f * 2 + 1) * NBINS + binB];
        unsigned long long cB2 = CpB[f * NBINS + binB];
        #pragma unroll
        for (int j = 0; j < 7; j++) {
            int row = f * KPB + kbase + j;      // 48B rows
            ulonglong2 x0 = Xp2[row * 3 + 0];
            ulonglong2 x1 = Xp2[row * 3 + 1];
            unsigned long long x2 = Xp1[row * 6 + 4];
            fma2(accA[j], x0.x, cA0.x);
            fma2(accB[j], x0.x, cB0.x);
            fma2(accA[j], x0.y, cA0.y);
            fma2(accB[j], x0.y, cB0.y);
            fma2(accA[j], x1.x, cA1.x);
            fma2(accB[j], x1.x, cB1.x);
            fma2(accA[j], x1.y, cA1.y);
            fma2(accB[j], x1.y, cB1.y);
            fma2(accA[j], x2, cA2);
            fma2(accB[j], x2, cB2);
        }
    }
    __syncthreads();   // X dead; smem flips to logits/MLP view

    float bbA = bias[binA];
    float bbB = bias[binB];
    #pragma unroll
    for (int j = 0; j < 7; j++) {
        float2 pa = unpack2(accA[j]);
        float2 pb = unpack2(accB[j]);
        sm[(kbase + j) * NBINS + binA] = pa.x + pa.y + bbA;
        sm[(kbase + j) * NBINS + binB] = pb.x + pb.y + bbB;
    }

    // ---- Phase 3: stage W1 (stride 132: 16B-aligned, 4-way max conflict), b1, W2 ----
    for (int i = tid; i < MLPH * NBINS; i += TPB)
        sm[OFF_W1 + (i >> 7) * 132 + (i & 127)] = W1[i];
    if (tid < MLPH) {
        sm[OFF_B1W2 + tid]        = b1[tid];
        sm[OFF_B1W2 + MLPH + tid] = W2[tid];
    }
    __syncthreads();

    // ---- Phase 4: layer 1 (relu) with W2 folded in, float4-vectorized ----
    #pragma unroll
    for (int t = 0; t < KPB * MLPH; t += TPB) {
        int task = t + tid;
        int kk = task >> 6;
        int j  = task & 63;
        float a = sm[OFF_B1W2 + j];
        const float4* lr = (const float4*)&sm[kk * NBINS];
        const float4* wr = (const float4*)&sm[OFF_W1 + j * 132];
        float a2 = 0.f, a3 = 0.f, a4 = 0.f;
        #pragma unroll 8
        for (int b = 0; b < 32; b++) {
            float4 x = lr[b];
            float4 w = wr[b];
            a  = fmaf(x.x, w.x, a);
            a2 = fmaf(x.y, w.y, a2);
            a3 = fmaf(x.z, w.z, a3);
            a4 = fmaf(x.w, w.w, a4);
        }
        a = (a + a2) + (a3 + a4);
        a = fmaxf(a, 0.f);
        sm[OFF_H + kk * MLPH + j] = a * sm[OFF_B1W2 + MLPH + j];
    }
    __syncthreads();

    // ---- Phase 5: reduce, position weight, sigmoid ----
    if (tid < KPB && (key0 + tid) < n) {
        float s = b2[0];
        #pragma unroll 16
        for (int j = 0; j < MLPH; j++) s += sm[OFF_H + tid * MLPH + j];

        int p = pos[key0 + tid];
        float lp = log10f(fmaxf((float)p, 1.0f));
        float a0 = log1pf(expf(araw[0]));
        float a1 = log1pf(expf(araw[1]));
        float a2 = log1pf(expf(araw[2]));
        float w;
        if (lp < 3.f)      w = a0;
        else if (lp < 4.f) w = a0 + (a1 - a0) * (lp - 3.f);
        else if (lp < 5.f) w = a1 + (a2 - a1) * (lp - 4.f);
        else               w = a2;

        float z = s * w;
        out[key0 + tid] = 1.f / (1.f + expf(-z));
    }
}

extern "C" void kernel_launch(void* const* d_in, const int* in_sizes, int n_in,
                              void* d_out, int out_size) {
    const float* K      = (const float*)d_in[0];
    const int*   pos    = (const int*)  d_in[1];
    const float* ra     = (const float*)d_in[2];
    const float* mu     = (const float*)d_in[3];
    const float* kappa  = (const float*)d_in[4];
    const float* weight = (const float*)d_in[5];
    const float* bias   = (const float*)d_in[6];
    const float* W1     = (const float*)d_in[7];
    const float* b1     = (const float*)d_in[8];
    const float* W2     = (const float*)d_in[9];
    const float* b2     = (const float*)d_in[10];
    const float* araw   = (const float*)d_in[11];

    int n = in_sizes[1];   // number of keys

    static int smem_set = 0;
    if (!smem_set) {
        cudaFuncSetAttribute(key_pruning_main,
                             cudaFuncAttributeMaxDynamicSharedMemorySize, SMEM_BYTES);
        smem_set = 1;
    }

    precompute_fourier<<<(NBINS * NFREQ + 127) / 128, 128>>>(mu, kappa, weight, ra);

    int grid = (n + KPB - 1) / KPB;
    key_pruning_main<<<grid, TPB, SMEM_BYTES>>>((const float2*)K, pos, bias, W1, b1, W2, b2, araw,
                                                (float*)d_out, n);
}

// round 8
// speedup vs baseline: 1.8293x; 1.2827x over previous
#include <cuda_runtime.h>
#include <cuda_bf16.h>
#include <math.h>

#define NBINS 128
#define NFREQ 64
#define NKERN 3
#define MLPH  64
#define KPB   28   // keys per block -> grid 293; 2 blocks/SM
#define TPB   256

typedef unsigned long long ull;

// Planar coefficient table: g_C[f][coord][bin], coord 0..8 =
//   [A0, A1c, A1s, A2c, A2s, A3c, A3s, A4c, A4s]
// pairing with features [m, mc1, ms1, mc2, ms2, mc3, ms3, mc4, ms4].
__device__ float4 g_C4[NFREQ * 9 * NBINS / 4];

__device__ __forceinline__ void fma2(ull& acc, ull a, ull b) {
    asm("fma.rn.f32x2 %0, %1, %2, %0;" : "+l"(acc) : "l"(a), "l"(b));
}
__device__ __forceinline__ ull dup2(float v) {
    ull r;
    asm("mov.b64 %0, {%1, %1};" : "=l"(r) : "f"(v));
    return r;
}
__device__ __forceinline__ float2 unpack2(ull v) {
    float2 r;
    asm("mov.b64 {%0, %1}, %2;" : "=f"(r.x), "=f"(r.y) : "l"(v));
    return r;
}

__global__ void precompute_fourier(const float* __restrict__ mu,
                                   const float* __restrict__ kappa,
                                   const float* __restrict__ weight,
                                   const float* __restrict__ ref_angles) {
    int idx = blockIdx.x * blockDim.x + threadIdx.x;
    if (idx >= NBINS * NFREQ) return;
    int b = idx / NFREQ;
    int f = idx % NFREQ;
    float C[9];
    #pragma unroll
    for (int i = 0; i < 9; i++) C[i] = 0.f;

    #pragma unroll
    for (int m = 0; m < NKERN; m++) {
        int off = (b * NFREQ + f) * NKERN + m;
        float kp = kappa[off];
        float w  = weight[off];
        float me = mu[off] + ref_angles[f];
        float h  = 0.5f * kp;
        float h2 = h * h;
        float ek = __expf(-kp);
        float I[5];
        float hk = 1.f, kfact = 1.f;
        #pragma unroll
        for (int kk = 0; kk < 5; kk++) {
            if (kk > 0) { hk *= h; kfact *= (float)kk; }
            float term = hk / kfact;
            float s = term;
            #pragma unroll
            for (int t = 1; t <= 8; t++) {
                term *= h2 / ((float)t * (float)(t + kk));
                s += term;
            }
            I[kk] = s;
        }
        float cm, sm;
        __sincosf(me, &sm, &cm);
        float wek = w * ek;
        C[0] += wek * I[0];
        float ck = cm, sk = sm;
        #pragma unroll
        for (int kk = 1; kk <= 4; kk++) {
            float g = 2.f * wek * I[kk];
            C[2 * kk - 1] += g * ck;
            C[2 * kk]     += g * sk;
            float cn = ck * cm - sk * sm;
            float sn = sk * cm + ck * sm;
            ck = cn; sk = sn;
        }
    }
    float* gC = (float*)g_C4;
    #pragma unroll
    for (int c = 0; c < 9; c++)
        gC[(f * 9 + c) * NBINS + b] = C[c];
}

// dynamic smem (floats):
//   sl[28*128]                         @ 0      (3584)
//   union @ 3584:
//     phase 1/2: float4 X4[64*28]               (28672 B)
//     phase 3/4: w1T[128*66] | h[28*64] | b1w2[128]   (41472 B)
#define OFF_U    (KPB * NBINS)                 // 3584
#define OFF_H    (OFF_U + 128 * 66)            // 3584 + 8448
#define OFF_B1W2 (OFF_H + KPB * MLPH)
#define SMEM_BYTES ((OFF_B1W2 + 2 * MLPH) * 4) // 55808

__global__ __launch_bounds__(TPB, 2)
void key_pruning_main(const float2* __restrict__ K2,
                      const int*    __restrict__ pos,
                      const float*  __restrict__ bias,
                      const float*  __restrict__ W1,      // [64][128]
                      const float*  __restrict__ b1,
                      const float*  __restrict__ W2,
                      const float*  __restrict__ b2,
                      const float*  __restrict__ araw,
                      float*        __restrict__ out,
                      int n) {
    extern __shared__ float sm[];
    float4* X4 = (float4*)(sm + OFF_U);

    const int tid  = threadIdx.x;
    const int warp = tid >> 5;
    const int lane = tid & 31;
    const int key0 = blockIdx.x * KPB;

    // ---- Phase 1: compact features {mag, 2*c1, x, y} (x = mag*cos, y = mag*sin) ----
    for (int i = tid; i < KPB * NFREQ; i += TPB) {
        int kk = i / NFREQ;
        int f  = i & (NFREQ - 1);
        int key = key0 + kk; if (key >= n) key = n - 1;
        float2 v = K2[key * NFREQ + f];
        float r2 = fmaf(v.x, v.x, v.y * v.y);
        r2 = fmaxf(r2, 1e-30f);
        float rinv = rsqrtf(r2);
        float mag = r2 * rinv;
        float c1x2 = 2.f * v.x * rinv;
        X4[f * KPB + kk] = make_float4(mag, c1x2, v.x, v.y);
    }
    __syncthreads();

    // ---- Phase 2: logits GEMM. warp = 28 keys x 32 bins; f split across warp-halves.
    //      Thread: 7 keys x 4 bins (2 bin-pair packed acc per key). Compute-bound. ----
    const int fbase = (warp >= 4) ? 32 : 0;
    const int wb    = (warp & 3) * 32;
    const int kq    = lane >> 3;
    const int b0    = wb + (lane & 7) * 4;   // thread bins b0..b0+3
    const int kbase = kq * 7;

    ull acc[14];
    #pragma unroll
    for (int i = 0; i < 14; i++) acc[i] = 0ull;

    const float* gC = (const float*)g_C4;

    for (int fo = 0; fo < 32; fo++) {
        int f = fbase + fo;
        const float* Cf = gC + f * 9 * NBINS + b0;
        ulonglong2 Cc[9];
        #pragma unroll
        for (int c = 0; c < 9; c++)
            Cc[c] = *(const ulonglong2*)(Cf + c * NBINS);
        #pragma unroll
        for (int j = 0; j < 7; j++) {
            float4 x = X4[f * KPB + kbase + j];
            float xs0 = x.x;                        // m
            float c1x2 = x.y;
            float xs1 = x.z;                        // m*cos1
            float xs2 = x.w;                        // m*sin1
            float xs3 = fmaf(c1x2, xs1, -xs0);      // m*cos2
            float xs4 = 0.5f * c1x2 * xs2 * 2.f;    // m*sin2 = 2*c1*(m*sin1)
            xs4 = c1x2 * xs2;
            float xs5 = fmaf(c1x2, xs3, -xs1);      // m*cos3
            float xs6 = fmaf(c1x2, xs4, -xs2);      // m*sin3
            float xs7 = fmaf(c1x2, xs5, -xs3);      // m*cos4
            float xs8 = fmaf(c1x2, xs6, -xs4);      // m*sin4
            ull* a = &acc[2 * j];
            #define STEP(c, v) { ull d = dup2(v); fma2(a[0], d, Cc[c].x); fma2(a[1], d, Cc[c].y); }
            STEP(0, xs0) STEP(1, xs1) STEP(2, xs2) STEP(3, xs3) STEP(4, xs4)
            STEP(5, xs5) STEP(6, xs6) STEP(7, xs7) STEP(8, xs8)
            #undef STEP
        }
    }

    // f-split reduction into sl (low-f warps write with bias; high-f warps add)
    float4 bias4 = *(const float4*)&bias[b0];
    if (warp < 4) {
        #pragma unroll
        for (int j = 0; j < 7; j++) {
            float2 p0 = unpack2(acc[2 * j]);
            float2 p1 = unpack2(acc[2 * j + 1]);
            float4 o = make_float4(p0.x + bias4.x, p0.y + bias4.y,
                                   p1.x + bias4.z, p1.y + bias4.w);
            *(float4*)&sm[(kbase + j) * NBINS + b0] = o;
        }
    }
    __syncthreads();
    if (warp >= 4) {
        #pragma unroll
        for (int j = 0; j < 7; j++) {
            float2 p0 = unpack2(acc[2 * j]);
            float2 p1 = unpack2(acc[2 * j + 1]);
            float4 cur = *(float4*)&sm[(kbase + j) * NBINS + b0];
            cur.x += p0.x; cur.y += p0.y; cur.z += p1.x; cur.w += p1.y;
            *(float4*)&sm[(kbase + j) * NBINS + b0] = cur;
        }
    } else {
        // ---- Phase 3 (overlapped): stage transposed W1 [k][h], stride 66 ----
        for (int i = tid; i < MLPH * NBINS; i += 128) {
            int h = i >> 7;
            int k = i & 127;
            sm[OFF_U + k * 66 + h] = W1[i];
        }
        if (tid < MLPH) {
            sm[OFF_B1W2 + tid]        = b1[tid];
            sm[OFF_B1W2 + MLPH + tid] = W2[tid];
        }
    }
    __syncthreads();

    // ---- Phase 4: MLP layer 1 on 128 threads: 7 keys x 2 hidden per thread ----
    if (tid < 128) {
        int pkq = tid >> 5;            // key quarter (uniform per warp)
        int hb  = (tid & 31) * 2;      // hidden pair
        float a[7][2];
        #pragma unroll
        for (int j = 0; j < 7; j++) { a[j][0] = 0.f; a[j][1] = 0.f; }
        #pragma unroll 4
        for (int k = 0; k < NBINS; k++) {
            float2 w = *(const float2*)&sm[OFF_U + k * 66 + hb];
            #pragma unroll
            for (int j = 0; j < 7; j++) {
                float l = sm[(pkq * 7 + j) * NBINS + k];
                a[j][0] = fmaf(l, w.x, a[j][0]);
                a[j][1] = fmaf(l, w.y, a[j][1]);
            }
        }
        float bb0 = sm[OFF_B1W2 + hb],        bb1 = sm[OFF_B1W2 + hb + 1];
        float w20 = sm[OFF_B1W2 + MLPH + hb], w21 = sm[OFF_B1W2 + MLPH + hb + 1];
        #pragma unroll
        for (int j = 0; j < 7; j++) {
            float h0 = fmaxf(a[j][0] + bb0, 0.f) * w20;
            float h1 = fmaxf(a[j][1] + bb1, 0.f) * w21;
            *(float2*)&sm[OFF_H + (pkq * 7 + j) * MLPH + hb] = make_float2(h0, h1);
        }
    }
    __syncthreads();

    // ---- Phase 5: reduce, position weight, sigmoid ----
    if (tid < KPB && (key0 + tid) < n) {
        float s = b2[0];
        const float4* hp = (const float4*)&sm[OFF_H + tid * MLPH];
        float s1 = 0.f, s2 = 0.f, s3 = 0.f;
        #pragma unroll
        for (int j = 0; j < MLPH / 4; j++) {
            float4 v = hp[j];
            s += v.x; s1 += v.y; s2 += v.z; s3 += v.w;
        }
        s = (s + s1) + (s2 + s3);

        int p = pos[key0 + tid];
        float lp = log10f(fmaxf((float)p, 1.0f));
        float a0 = log1pf(expf(araw[0]));
        float a1 = log1pf(expf(araw[1]));
        float a2 = log1pf(expf(araw[2]));
        float w;
        if (lp < 3.f)      w = a0;
        else if (lp < 4.f) w = a0 + (a1 - a0) * (lp - 3.f);
        else if (lp < 5.f) w = a1 + (a2 - a1) * (lp - 4.f);
        else               w = a2;

        float z = s * w;
        out[key0 + tid] = 1.f / (1.f + expf(-z));
    }
}

extern "C" void kernel_launch(void* const* d_in, const int* in_sizes, int n_in,
                              void* d_out, int out_size) {
    const float* K      = (const float*)d_in[0];
    const int*   pos    = (const int*)  d_in[1];
    const float* ra     = (const float*)d_in[2];
    const float* mu     = (const float*)d_in[3];
    const float* kappa  = (const float*)d_in[4];
    const float* weight = (const float*)d_in[5];
    const float* bias   = (const float*)d_in[6];
    const float* W1     = (const float*)d_in[7];
    const float* b1     = (const float*)d_in[8];
    const float* W2     = (const float*)d_in[9];
    const float* b2     = (const float*)d_in[10];
    const float* araw   = (const float*)d_in[11];

    int n = in_sizes[1];   // number of keys

    static int smem_set = 0;
    if (!smem_set) {
        cudaFuncSetAttribute(key_pruning_main,
                             cudaFuncAttributeMaxDynamicSharedMemorySize, SMEM_BYTES);
        smem_set = 1;
    }

    precompute_fourier<<<(NBINS * NFREQ + 127) / 128, 128>>>(mu, kappa, weight, ra);

    int grid = (n + KPB - 1) / KPB;
    key_pruning_main<<<grid, TPB, SMEM_BYTES>>>((const float2*)K, pos, bias, W1, b1, W2, b2, araw,
                                                (float*)d_out, n);
}